// round 13
// baseline (speedup 1.0000x reference)
#include <cuda_runtime.h>
#include <math.h>
#include <stdint.h>

#define DD 280
#define HH 7
#define HDD 40
#define LL 7
#define FFD 1120
#define VV 256
#define TT 512
#define BB 32
#define MM (BB*TT)   // 16384

// ---------------- scratch (device globals; no allocation allowed) ----------------
__device__ float g_x[MM*DD];
__device__ float g_h[MM*DD];
__device__ float g_q[MM*DD];
__device__ float g_k[MM*DD];
__device__ float g_v[MM*DD];
__device__ float g_o[MM*DD];
__device__ float g_gp[(size_t)MM*FFD];
__device__ float g_ct[TT*20];
__device__ float g_st[TT*20];
// rounded weights: wq|wk|wv|wo (7*78400 each) | w1|w3|w2 (7*313600 each) | emb (71680)
#define WR_Q 0
#define WR_K 548800
#define WR_V 1097600
#define WR_O 1646400
#define WR_1 2195200
#define WR_3 4390400
#define WR_2 6585600
#define WR_E 8780800
__device__ float g_wr[8852480];

// ---------------- helpers ----------------
__device__ __forceinline__ float to_tf32(float x) {
    unsigned u;
    asm("cvt.rna.tf32.f32 %0, %1;" : "=r"(u) : "f"(x));
    return __uint_as_float(u);
}
__device__ __forceinline__ uint32_t smem_u32(const void* p) {
    uint32_t a;
    asm("{ .reg .u64 t; cvta.to.shared.u64 t, %1; cvt.u32.u64 %0, t; }" : "=r"(a) : "l"(p));
    return a;
}
__device__ __forceinline__ void mma8(float* d, const uint32_t* a, const uint32_t* b) {
    asm volatile(
        "mma.sync.aligned.m16n8k8.row.col.f32.tf32.tf32.f32 "
        "{%0,%1,%2,%3}, {%4,%5,%6,%7}, {%8,%9}, {%0,%1,%2,%3};\n"
        : "+f"(d[0]), "+f"(d[1]), "+f"(d[2]), "+f"(d[3])
        : "r"(a[0]), "r"(a[1]), "r"(a[2]), "r"(a[3]), "r"(b[0]), "r"(b[1]));
}
#define LDM4(r, addr) \
    asm volatile("ldmatrix.sync.aligned.m8n8.x4.shared.b16 {%0,%1,%2,%3}, [%4];" \
        : "=r"((r)[0]), "=r"((r)[1]), "=r"((r)[2]), "=r"((r)[3]) : "r"(addr))

__device__ __forceinline__ void cp16(uint32_t dst, const void* src, unsigned sz) {
    asm volatile("cp.async.cg.shared.global [%0], [%1], 16, %2;"
                 :: "r"(dst), "l"(src), "r"(sz) : "memory");
}
#define CP_COMMIT() asm volatile("cp.async.commit_group;" ::: "memory")
#define CP_WAIT(n)  asm volatile("cp.async.wait_group %0;" :: "n"(n) : "memory")

// ---------------- weight pre-round: dst = tf32(src), float4 ----------------
__global__ void k_round(const float* __restrict__ src, float* __restrict__ dst, int n4) {
    int i = blockIdx.x * 256 + threadIdx.x;
    if (i >= n4) return;
    float4 v = *(const float4*)(src + (size_t)i * 4);
    v.x = to_tf32(v.x); v.y = to_tf32(v.y); v.z = to_tf32(v.z); v.w = to_tf32(v.w);
    *(float4*)(dst + (size_t)i * 4) = v;
}

// ============ tensor-core GEMM: C[M,N] = A[M,K] * W[N,K]^T (opt +=) ============
// Inputs A and W must be pre-rounded tf32 in gmem; cp.async 4-stage pipeline.
#define AS_STG 18432   // 128*36*4
#define WS_STG 9216    // 64*36*4
#define S_GEMM 4
#define SMEM_GEMM (S_GEMM*(AS_STG+WS_STG))   // 110592

template<bool ADD>
__global__ void __launch_bounds__(256) k_gemm_tc(
        const float* __restrict__ A,
        const float* __restrict__ Wa, const float* __restrict__ Wb, const float* __restrict__ Wc,
        float* __restrict__ Ca, float* __restrict__ Cb, float* __restrict__ Cc,
        int N, int K) {
    const float* W = (blockIdx.z == 0) ? Wa : ((blockIdx.z == 1) ? Wb : Wc);
    float*       C = (blockIdx.z == 0) ? Ca : ((blockIdx.z == 1) ? Cb : Cc);
    extern __shared__ __align__(16) char smem[];
    uint32_t sA = smem_u32(smem);
    uint32_t sW = sA + S_GEMM * AS_STG;

    int m0 = blockIdx.y * 128, n0 = blockIdx.x * 64;
    int tid = threadIdx.x;
    int lane = tid & 31, warp = tid >> 5;
    int wm = (warp & 3) * 32, wn = (warp >> 2) * 32;
    int g = lane >> 2, q = lane & 3;

    int arow = (lane & 7) + ((lane >> 3) & 1) * 8;
    int acol = (lane >> 4) * 4;
    int brow = (lane & 7) + (lane >> 4) * 8;
    int bcol = ((lane >> 3) & 1) * 4;
    uint32_t aAddr = sA + (uint32_t)((wm + arow) * 36 + acol) * 4;
    uint32_t bAddr = sW + (uint32_t)((wn + brow) * 36 + bcol) * 4;

    // per-thread cp.async coordinates
    int crow = tid >> 3, cf4 = tid & 7;          // A: rows crow, crow+32, crow+64, crow+96
    uint32_t aDst = sA + (uint32_t)(crow * 36 + cf4 * 4) * 4;
    uint32_t bDst = sW + (uint32_t)(crow * 36 + cf4 * 4) * 4;

    int NC = (K + 31) >> 5;

    auto issue = [&](int c, int buf) {
        int kk = (c << 5) + cf4 * 4;
        unsigned okk = (kk + 4 <= K) ? 16u : 0u;
        const float* ap = A + (size_t)(m0 + crow) * K + (okk ? kk : 0);
        #pragma unroll
        for (int r = 0; r < 4; r++) {
            cp16(aDst + (uint32_t)buf * AS_STG + (uint32_t)r * 32 * 144,
                 ap + (size_t)r * 32 * K, okk);
        }
        #pragma unroll
        for (int r = 0; r < 2; r++) {
            int row = n0 + crow + r * 32;
            unsigned sz = (okk && row < N) ? 16u : 0u;
            const float* wp = W + (sz ? ((size_t)row * K + kk) : 0);
            cp16(bDst + (uint32_t)buf * WS_STG + (uint32_t)r * 32 * 144, wp, sz);
        }
    };

    float acc[2][4][4] = {};

    #pragma unroll
    for (int c = 0; c < S_GEMM - 1; c++) {
        if (c < NC) issue(c, c);
        CP_COMMIT();
    }

    for (int c = 0; c < NC; c++) {
        CP_WAIT(S_GEMM - 2);
        __syncthreads();
        int cn = c + S_GEMM - 1;
        if (cn < NC) issue(cn, cn & (S_GEMM - 1));
        CP_COMMIT();

        uint32_t aOff = aAddr + (uint32_t)(c & (S_GEMM - 1)) * AS_STG;
        uint32_t bOff = bAddr + (uint32_t)(c & (S_GEMM - 1)) * WS_STG;
        #pragma unroll
        for (int s = 0; s < 4; s++) {
            uint32_t ko = s * 32;
            uint32_t a0[4], a1[4], b0[4], b1[4];
            LDM4(a0, aOff + ko);
            LDM4(a1, aOff + ko + 16 * 144);
            LDM4(b0, bOff + ko);
            LDM4(b1, bOff + ko + 16 * 144);
            mma8(acc[0][0], a0, b0);     mma8(acc[0][1], a0, b0 + 2);
            mma8(acc[0][2], a0, b1);     mma8(acc[0][3], a0, b1 + 2);
            mma8(acc[1][0], a1, b0);     mma8(acc[1][1], a1, b0 + 2);
            mma8(acc[1][2], a1, b1);     mma8(acc[1][3], a1, b1 + 2);
        }
    }

    #pragma unroll
    for (int mt = 0; mt < 2; mt++) {
        int r0 = m0 + wm + mt * 16 + g;
        #pragma unroll
        for (int nt = 0; nt < 4; nt++) {
            int c0 = n0 + wn + nt * 8 + 2 * q;
            if (c0 < N) {
                float* d = acc[mt][nt];
                size_t o1 = (size_t)r0 * N + c0;
                size_t o2 = (size_t)(r0 + 8) * N + c0;
                if (ADD) {
                    C[o1] += d[0]; C[o1 + 1] += d[1];
                    C[o2] += d[2]; C[o2 + 1] += d[3];
                } else {
                    C[o1] = d[0]; C[o1 + 1] = d[1];
                    C[o2] = d[2]; C[o2 + 1] = d[3];
                }
            }
        }
    }
}

// ============ fused MLP GEMM: Gp = tf32(silu(A*W1^T) * (A*W3^T)) ============
#define S_MLP 3
#define SMEM_MLP (S_MLP*(AS_STG+2*WS_STG))   // 110592

__global__ void __launch_bounds__(256) k_mlp_tc(
        const float* __restrict__ A,
        const float* __restrict__ W1, const float* __restrict__ W3,
        float* __restrict__ Gp) {
    const int N = FFD, K = DD;
    extern __shared__ __align__(16) char smem[];
    uint32_t sA  = smem_u32(smem);
    uint32_t sW1 = sA + S_MLP * AS_STG;
    uint32_t sW3 = sW1 + S_MLP * WS_STG;

    int m0 = blockIdx.y * 128, n0 = blockIdx.x * 64;
    int tid = threadIdx.x;
    int lane = tid & 31, warp = tid >> 5;
    int wm = (warp & 3) * 32, wn = (warp >> 2) * 32;
    int g = lane >> 2, q = lane & 3;

    int arow = (lane & 7) + ((lane >> 3) & 1) * 8;
    int acol = (lane >> 4) * 4;
    int brow = (lane & 7) + (lane >> 4) * 8;
    int bcol = ((lane >> 3) & 1) * 4;
    uint32_t aAddr  = sA  + (uint32_t)((wm + arow) * 36 + acol) * 4;
    uint32_t b1Addr = sW1 + (uint32_t)((wn + brow) * 36 + bcol) * 4;
    uint32_t b3Addr = sW3 + (uint32_t)((wn + brow) * 36 + bcol) * 4;

    int crow = tid >> 3, cf4 = tid & 7;
    uint32_t aDst = sA  + (uint32_t)(crow * 36 + cf4 * 4) * 4;
    uint32_t wDst =       (uint32_t)(crow * 36 + cf4 * 4) * 4;

    int NC = (K + 31) >> 5;   // 9

    auto issue = [&](int c, int buf) {
        int kk = (c << 5) + cf4 * 4;
        unsigned okk = (kk + 4 <= K) ? 16u : 0u;
        const float* ap = A + (size_t)(m0 + crow) * K + (okk ? kk : 0);
        #pragma unroll
        for (int r = 0; r < 4; r++) {
            cp16(aDst + (uint32_t)buf * AS_STG + (uint32_t)r * 32 * 144,
                 ap + (size_t)r * 32 * K, okk);
        }
        #pragma unroll
        for (int r = 0; r < 2; r++) {
            int row = n0 + crow + r * 32;
            unsigned sz = (okk && row < N) ? 16u : 0u;
            size_t off = sz ? ((size_t)row * K + kk) : 0;
            cp16(sW1 + wDst + (uint32_t)buf * WS_STG + (uint32_t)r * 32 * 144, W1 + off, sz);
            cp16(sW3 + wDst + (uint32_t)buf * WS_STG + (uint32_t)r * 32 * 144, W3 + off, sz);
        }
    };

    float acc1[2][4][4] = {};
    float acc3[2][4][4] = {};

    #pragma unroll
    for (int c = 0; c < S_MLP - 1; c++) {
        if (c < NC) issue(c, c);
        CP_COMMIT();
    }

    for (int c = 0; c < NC; c++) {
        CP_WAIT(S_MLP - 2);
        __syncthreads();
        int cn = c + S_MLP - 1;
        if (cn < NC) issue(cn, cn % S_MLP);
        CP_COMMIT();

        int buf = c % S_MLP;
        uint32_t aOff  = aAddr  + (uint32_t)buf * AS_STG;
        uint32_t b1Off = b1Addr + (uint32_t)buf * WS_STG;
        uint32_t b3Off = b3Addr + (uint32_t)buf * WS_STG;
        #pragma unroll
        for (int s = 0; s < 4; s++) {
            uint32_t ko = s * 32;
            uint32_t a0[4], a1[4], b0[4], b1[4], c0[4], c1[4];
            LDM4(a0, aOff + ko);
            LDM4(a1, aOff + ko + 16 * 144);
            LDM4(b0, b1Off + ko);
            LDM4(b1, b1Off + ko + 16 * 144);
            LDM4(c0, b3Off + ko);
            LDM4(c1, b3Off + ko + 16 * 144);
            mma8(acc1[0][0], a0, b0);  mma8(acc1[0][1], a0, b0 + 2);
            mma8(acc1[0][2], a0, b1);  mma8(acc1[0][3], a0, b1 + 2);
            mma8(acc1[1][0], a1, b0);  mma8(acc1[1][1], a1, b0 + 2);
            mma8(acc1[1][2], a1, b1);  mma8(acc1[1][3], a1, b1 + 2);
            mma8(acc3[0][0], a0, c0);  mma8(acc3[0][1], a0, c0 + 2);
            mma8(acc3[0][2], a0, c1);  mma8(acc3[0][3], a0, c1 + 2);
            mma8(acc3[1][0], a1, c0);  mma8(acc3[1][1], a1, c0 + 2);
            mma8(acc3[1][2], a1, c1);  mma8(acc3[1][3], a1, c1 + 2);
        }
    }

    #pragma unroll
    for (int mt = 0; mt < 2; mt++) {
        int r0 = m0 + wm + mt * 16 + g;
        #pragma unroll
        for (int nt = 0; nt < 4; nt++) {
            int c0 = n0 + wn + nt * 8 + 2 * q;
            if (c0 < N) {
                float* dg = acc1[mt][nt];
                float* du = acc3[mt][nt];
                #pragma unroll
                for (int e = 0; e < 4; e++) {
                    float gg = dg[e], uu = du[e];
                    float sv = gg / (1.f + __expf(-gg));
                    int row = (e < 2) ? r0 : r0 + 8;
                    int col = c0 + (e & 1);
                    Gp[(size_t)row * N + col] = to_tf32(sv * uu);
                }
            }
        }
    }
}

// ---------------- embed ----------------
__global__ void k_embed(const int* __restrict__ idx, const float* __restrict__ emb,
                        float* __restrict__ x) {
    int i = blockIdx.x * 256 + threadIdx.x;
    if (i >= MM * DD) return;
    int m = i / DD;
    int d = i - m * DD;
    x[i] = emb[idx[m] * DD + d];
}

// ---------------- rope table ----------------
__global__ void k_rope(float* __restrict__ ct, float* __restrict__ st) {
    int i = blockIdx.x * 256 + threadIdx.x;
    if (i >= TT * 20) return;
    int t = i / 20, p = i % 20;
    float f = expf(-0.4605170186f * (float)p);   // 10000^{-p/20}
    float s, c;
    sincosf((float)t * f, &s, &c);
    ct[i] = c;
    st[i] = s;
}

// ---------------- rmsnorm: warp per row, 8 rows/block; output pre-rounded ----------------
__global__ void __launch_bounds__(256) k_rmsnorm(const float* __restrict__ x,
                                                 const float* __restrict__ w,
                                                 float* __restrict__ out) {
    int m = blockIdx.x * 8 + (threadIdx.x >> 5);
    int lane = threadIdx.x & 31;
    const float* xr = x + (size_t)m * DD;
    float v[9];
    float ss = 0.f;
    #pragma unroll
    for (int j = 0; j < 9; j++) {
        int d = lane + 32 * j;
        v[j] = (d < DD) ? xr[d] : 0.f;
        ss += v[j] * v[j];
    }
    #pragma unroll
    for (int o = 16; o; o >>= 1) ss += __shfl_xor_sync(0xffffffffu, ss, o);
    float sc = rsqrtf(ss / (float)DD + 1e-6f);
    float* orow = out + (size_t)m * DD;
    #pragma unroll
    for (int j = 0; j < 9; j++) {
        int d = lane + 32 * j;
        if (d < DD) orow[d] = to_tf32(v[j] * sc * w[d]);
    }
}

// ============ fused flash attention (rotary on load; output pre-rounded) ============
__global__ void __launch_bounds__(256) k_attn(const float* __restrict__ q,
                                              const float* __restrict__ k,
                                              const float* __restrict__ v,
                                              float* __restrict__ o,
                                              const float* __restrict__ ct,
                                              const float* __restrict__ st) {
    int tt0 = blockIdx.x * 64;
    int bh = blockIdx.y;
    int b = bh / HH, h = bh - b * HH;
    const float* qb = q + (size_t)b * TT * DD + h * HDD;
    const float* kb = k + (size_t)b * TT * DD + h * HDD;
    const float* vb = v + (size_t)b * TT * DD + h * HDD;
    float* ob       = o + ((size_t)b * TT + tt0) * DD + h * HDD;

    __shared__ float Qs[64][41];
    __shared__ float Ks[32][41];
    __shared__ float Vs[32][41];
    __shared__ float Ps[64][33];
    __shared__ float s_m[64], s_l[64], s_al[64];

    int tid = threadIdx.x;
    int lane = tid & 31, warp = tid >> 5;
    int tx = tid & 7, ty = tid >> 3;
    const float scale = 0.1581138830f;   // 40^-0.5

    for (int i = tid; i < 64 * HDD; i += 256) {
        int r = i / HDD, c = i - r * HDD;
        int t = tt0 + r;
        int p = (c < 20) ? c : c - 20;
        float cv = ct[t * 20 + p], sv = st[t * 20 + p];
        float a  = qb[(size_t)t * DD + c];
        float b2 = (c < 20) ? qb[(size_t)t * DD + c + 20] : qb[(size_t)t * DD + c - 20];
        float val = (c < 20) ? (a * cv - b2 * sv) : (a * cv + b2 * sv);
        Qs[r][c] = val * scale;
    }
    if (tid < 64) { s_m[tid] = -3.0e38f; s_l[tid] = 0.f; }
    __syncthreads();

    float accO[2][5] = {};
    int send = tt0 + 64;

    for (int s0 = 0; s0 < send; s0 += 32) {
        for (int i = tid; i < 32 * HDD; i += 256) {
            int r = i / HDD, c = i - r * HDD;
            int t = s0 + r;
            int p = (c < 20) ? c : c - 20;
            float cv = ct[t * 20 + p], sv = st[t * 20 + p];
            float a  = kb[(size_t)t * DD + c];
            float b2 = (c < 20) ? kb[(size_t)t * DD + c + 20] : kb[(size_t)t * DD + c - 20];
            Ks[r][c] = (c < 20) ? (a * cv - b2 * sv) : (a * cv + b2 * sv);
            Vs[r][c] = vb[(size_t)t * DD + c];
        }
        __syncthreads();

        // --- scores: warp handles 8 q-rows, lane = s within chunk ---
        float kreg[HDD];
        #pragma unroll
        for (int d = 0; d < HDD; d++) kreg[d] = Ks[lane][d];
        int sglob = s0 + lane;
        int r0 = warp * 8;
        #pragma unroll
        for (int ri = 0; ri < 8; ri++) {
            int rglob = tt0 + r0 + ri;
            float acc = 0.f;
            #pragma unroll
            for (int d = 0; d < HDD; d++) acc += Qs[r0 + ri][d] * kreg[d];
            float sv = (sglob <= rglob) ? acc : -1.0e30f;
            float mx = sv;
            #pragma unroll
            for (int off = 16; off; off >>= 1)
                mx = fmaxf(mx, __shfl_xor_sync(0xffffffffu, mx, off));
            float mold = s_m[r0 + ri];
            float mnew = fmaxf(mold, mx);
            float p = __expf(sv - mnew);
            float ps = p;
            #pragma unroll
            for (int off = 16; off; off >>= 1)
                ps += __shfl_xor_sync(0xffffffffu, ps, off);
            Ps[r0 + ri][lane] = p;
            if (lane == 0) {
                float al = __expf(mold - mnew);
                s_al[r0 + ri] = al;
                s_m[r0 + ri]  = mnew;
                s_l[r0 + ri]  = al * s_l[r0 + ri] + ps;
            }
        }
        __syncthreads();

        // --- O update: thread = (2 rows ty, 5 d-cols tx) ---
        float a0 = s_al[ty * 2], a1 = s_al[ty * 2 + 1];
        #pragma unroll
        for (int j = 0; j < 5; j++) { accO[0][j] *= a0; accO[1][j] *= a1; }
        #pragma unroll
        for (int kk = 0; kk < 32; kk++) {
            float p0 = Ps[ty * 2][kk];
            float p1 = Ps[ty * 2 + 1][kk];
            #pragma unroll
            for (int j = 0; j < 5; j++) {
                float vv = Vs[kk][tx * 5 + j];
                accO[0][j] += p0 * vv;
                accO[1][j] += p1 * vv;
            }
        }
        __syncthreads();
    }

    float inv0 = 1.f / s_l[ty * 2];
    float inv1 = 1.f / s_l[ty * 2 + 1];
    #pragma unroll
    for (int j = 0; j < 5; j++) {
        ob[(size_t)(ty * 2 + 0) * DD + tx * 5 + j] = to_tf32(accO[0][j] * inv0);
        ob[(size_t)(ty * 2 + 1) * DD + tx * 5 + j] = to_tf32(accO[1][j] * inv1);
    }
}

// ---------------- launcher ----------------
extern "C" void kernel_launch(void* const* d_in, const int* in_sizes, int n_in,
                              void* d_out, int out_size) {
    const int*   idx = (const int*)  d_in[0];
    const float* emb = (const float*)d_in[1];
    const float* wq  = (const float*)d_in[2];
    const float* wk  = (const float*)d_in[3];
    const float* wv  = (const float*)d_in[4];
    const float* wo  = (const float*)d_in[5];
    const float* w1  = (const float*)d_in[6];
    const float* w2  = (const float*)d_in[7];
    const float* w3  = (const float*)d_in[8];
    const float* n1  = (const float*)d_in[9];
    const float* n2  = (const float*)d_in[10];
    const float* nw  = (const float*)d_in[11];
    float* out = (float*)d_out;

    float *x, *h, *q, *k, *v, *o, *gp, *ct, *st, *wr;
    cudaGetSymbolAddress((void**)&x,  g_x);
    cudaGetSymbolAddress((void**)&h,  g_h);
    cudaGetSymbolAddress((void**)&q,  g_q);
    cudaGetSymbolAddress((void**)&k,  g_k);
    cudaGetSymbolAddress((void**)&v,  g_v);
    cudaGetSymbolAddress((void**)&o,  g_o);
    cudaGetSymbolAddress((void**)&gp, g_gp);
    cudaGetSymbolAddress((void**)&ct, g_ct);
    cudaGetSymbolAddress((void**)&st, g_st);
    cudaGetSymbolAddress((void**)&wr, g_wr);

    cudaFuncSetAttribute((const void*)k_gemm_tc<false>,
                         cudaFuncAttributeMaxDynamicSharedMemorySize, SMEM_GEMM);
    cudaFuncSetAttribute((const void*)k_gemm_tc<true>,
                         cudaFuncAttributeMaxDynamicSharedMemorySize, SMEM_GEMM);
    cudaFuncSetAttribute((const void*)k_mlp_tc,
                         cudaFuncAttributeMaxDynamicSharedMemorySize, SMEM_MLP);

    // pre-round all weights once per launch
    const int NW_D = LL * DD * DD;    // 548800
    const int NW_F = LL * FFD * DD;   // 2195200
    k_round<<<(NW_D / 4 + 255) / 256, 256>>>(wq, wr + WR_Q, NW_D / 4);
    k_round<<<(NW_D / 4 + 255) / 256, 256>>>(wk, wr + WR_K, NW_D / 4);
    k_round<<<(NW_D / 4 + 255) / 256, 256>>>(wv, wr + WR_V, NW_D / 4);
    k_round<<<(NW_D / 4 + 255) / 256, 256>>>(wo, wr + WR_O, NW_D / 4);
    k_round<<<(NW_F / 4 + 255) / 256, 256>>>(w1, wr + WR_1, NW_F / 4);
    k_round<<<(NW_F / 4 + 255) / 256, 256>>>(w3, wr + WR_3, NW_F / 4);
    k_round<<<(NW_F / 4 + 255) / 256, 256>>>(w2, wr + WR_2, NW_F / 4);
    k_round<<<(VV * DD / 4 + 255) / 256, 256>>>(emb, wr + WR_E, VV * DD / 4);

    k_rope<<<(TT * 20 + 255) / 256, 256>>>(ct, st);
    k_embed<<<(MM * DD + 255) / 256, 256>>>(idx, emb, x);

    dim3 gQKV(5, MM / 128, 3);   // N = 280, 3 outputs
    dim3 gD  (5, MM / 128, 1);   // N = 280
    dim3 gF  (18, MM / 128);     // N = 1120 fused MLP
    dim3 gV  (4, MM / 128, 1);   // N = 256

    for (int l = 0; l < LL; l++) {
        size_t wOff = (size_t)l * DD * DD;
        size_t fOff = (size_t)l * FFD * DD;
        k_rmsnorm<<<MM / 8, 256>>>(x, n1 + l * DD, h);
        k_gemm_tc<false><<<gQKV, 256, SMEM_GEMM>>>(
            h, wr + WR_Q + wOff, wr + WR_K + wOff, wr + WR_V + wOff,
            q, k, v, DD, DD);
        k_attn<<<dim3(TT / 64, BB * HH), 256>>>(q, k, v, o, ct, st);
        k_gemm_tc<true><<<gD, 256, SMEM_GEMM>>>(
            o, wr + WR_O + wOff, 0, 0, x, 0, 0, DD, DD);
        k_rmsnorm<<<MM / 8, 256>>>(x, n2 + l * DD, h);
        k_mlp_tc<<<gF, 256, SMEM_MLP>>>(h, wr + WR_1 + fOff, wr + WR_3 + fOff, gp);
        k_gemm_tc<true><<<gD, 256, SMEM_GEMM>>>(
            gp, wr + WR_2 + fOff, 0, 0, x, 0, 0, DD, FFD);
    }

    k_rmsnorm<<<MM / 8, 256>>>(x, nw, h);
    k_gemm_tc<false><<<gV, 256, SMEM_GEMM>>>(
        h, wr + WR_E, 0, 0, out, 0, 0, VV, DD);
}

// round 14
// speedup vs baseline: 1.1788x; 1.1788x over previous
#include <cuda_runtime.h>
#include <cuda_fp16.h>
#include <math.h>
#include <stdint.h>

#define DD 280
#define HH 7
#define HDD 40
#define LL 7
#define FFD 1120
#define VV 256
#define TT 512
#define BB 32
#define MM (BB*TT)   // 16384

// ---------------- scratch (device globals; no allocation allowed) ----------------
__device__ float g_x[MM*DD];
__device__ __align__(16) __half g_h[MM*DD];
__device__ float g_q[MM*DD];
__device__ float g_k[MM*DD];
__device__ float g_v[MM*DD];
__device__ __align__(16) __half g_o[MM*DD];
__device__ __align__(16) __half g_gp[(size_t)MM*FFD];
__device__ float g_ct[TT*20];
__device__ float g_st[TT*20];
// rounded fp16 weights: wq|wk|wv|wo (7*78400 each) | w1|w3|w2 (7*313600 each) | emb
#define WR_Q 0
#define WR_K 548800
#define WR_V 1097600
#define WR_O 1646400
#define WR_1 2195200
#define WR_3 4390400
#define WR_2 6585600
#define WR_E 8780800
__device__ __align__(16) __half g_wr[8852480];

// ---------------- helpers ----------------
__device__ __forceinline__ uint32_t smem_u32(const void* p) {
    uint32_t a;
    asm("{ .reg .u64 t; cvta.to.shared.u64 t, %1; cvt.u32.u64 %0, t; }" : "=r"(a) : "l"(p));
    return a;
}
__device__ __forceinline__ void mma16(float* d, const uint32_t* a, const uint32_t* b) {
    asm volatile(
        "mma.sync.aligned.m16n8k16.row.col.f32.f16.f16.f32 "
        "{%0,%1,%2,%3}, {%4,%5,%6,%7}, {%8,%9}, {%0,%1,%2,%3};\n"
        : "+f"(d[0]), "+f"(d[1]), "+f"(d[2]), "+f"(d[3])
        : "r"(a[0]), "r"(a[1]), "r"(a[2]), "r"(a[3]), "r"(b[0]), "r"(b[1]));
}
#define LDM4(r, addr) \
    asm volatile("ldmatrix.sync.aligned.m8n8.x4.shared.b16 {%0,%1,%2,%3}, [%4];" \
        : "=r"((r)[0]), "=r"((r)[1]), "=r"((r)[2]), "=r"((r)[3]) : "r"(addr))

__device__ __forceinline__ void cp16(uint32_t dst, const void* src, unsigned sz) {
    asm volatile("cp.async.cg.shared.global [%0], [%1], 16, %2;"
                 :: "r"(dst), "l"(src), "r"(sz) : "memory");
}
#define CP_COMMIT() asm volatile("cp.async.commit_group;" ::: "memory")
#define CP_WAIT(n)  asm volatile("cp.async.wait_group %0;" :: "n"(n) : "memory")

// ---------------- weight pre-round: dst = fp16(src) ----------------
__global__ void k_round(const float* __restrict__ src, __half* __restrict__ dst, int n4) {
    int i = blockIdx.x * 256 + threadIdx.x;
    if (i >= n4) return;
    float4 v = *(const float4*)(src + (size_t)i * 4);
    __half2 h0 = __floats2half2_rn(v.x, v.y);
    __half2 h1 = __floats2half2_rn(v.z, v.w);
    __half2* d = (__half2*)(dst + (size_t)i * 4);
    d[0] = h0;
    d[1] = h1;
}

// ============ fp16 tensor-core GEMM: C[M,N] = A[M,K] * W[N,K]^T (opt +=) ============
// A, W are fp16 in gmem; fp32 accumulate; cp.async 4-stage pipeline; BK=64 halves.
#define RS 72                    // halves per SMEM row (144 B, conflict-free LDSM)
#define AS_STG (128*RS*2)        // 18432
#define WS_STG (64*RS*2)         // 9216
#define S_GEMM 4
#define SMEM_GEMM (S_GEMM*(AS_STG+WS_STG))   // 110592

template<bool ADD>
__global__ void __launch_bounds__(256) k_gemm_tc(
        const __half* __restrict__ A,
        const __half* __restrict__ Wa, const __half* __restrict__ Wb, const __half* __restrict__ Wc,
        float* __restrict__ Ca, float* __restrict__ Cb, float* __restrict__ Cc,
        int N, int K) {
    const __half* W = (blockIdx.z == 0) ? Wa : ((blockIdx.z == 1) ? Wb : Wc);
    float*        C = (blockIdx.z == 0) ? Ca : ((blockIdx.z == 1) ? Cb : Cc);
    extern __shared__ __align__(16) char smem[];
    uint32_t sA = smem_u32(smem);
    uint32_t sW = sA + S_GEMM * AS_STG;

    int m0 = blockIdx.y * 128, n0 = blockIdx.x * 64;
    int tid = threadIdx.x;
    int lane = tid & 31, warp = tid >> 5;
    int wm = (warp & 3) * 32, wn = (warp >> 2) * 32;
    int g = lane >> 2, q = lane & 3;

    // ldmatrix fragment addresses (fp16 m16n8k16 layout)
    int arow = (lane & 7) + ((lane >> 3) & 1) * 8;   // A groups: r0..r3 = a0..a3
    int acolh = (lane >> 4) * 8;
    int brow = (lane & 7) + (lane >> 4) * 8;         // B groups: r0,r1 = nt0; r2,r3 = nt1
    int bcolh = ((lane >> 3) & 1) * 8;
    uint32_t aAddr = sA + (uint32_t)((wm + arow) * RS + acolh) * 2;
    uint32_t bAddr = sW + (uint32_t)((wn + brow) * RS + bcolh) * 2;

    // cp.async per-thread coords: 8 x 16B segments per row (BK=64 halves)
    int crow = tid >> 3, c8 = tid & 7;
    uint32_t aDst = sA + (uint32_t)(crow * RS + c8 * 8) * 2;
    uint32_t bDst = sW + (uint32_t)(crow * RS + c8 * 8) * 2;

    int NC = (K + 63) >> 6;

    auto issue = [&](int c, int buf) {
        int kk = (c << 6) + c8 * 8;                  // in halves
        unsigned okk = (kk + 8 <= K) ? 16u : 0u;
        const __half* ap = A + (size_t)(m0 + crow) * K + (okk ? kk : 0);
        #pragma unroll
        for (int r = 0; r < 4; r++) {
            cp16(aDst + (uint32_t)buf * AS_STG + (uint32_t)r * 32 * RS * 2,
                 ap + (size_t)r * 32 * K, okk);
        }
        #pragma unroll
        for (int r = 0; r < 2; r++) {
            int row = n0 + crow + r * 32;
            unsigned sz = (okk && row < N) ? 16u : 0u;
            const __half* wp = W + (sz ? ((size_t)row * K + kk) : 0);
            cp16(bDst + (uint32_t)buf * WS_STG + (uint32_t)r * 32 * RS * 2, wp, sz);
        }
    };

    float acc[2][4][4] = {};

    #pragma unroll
    for (int c = 0; c < S_GEMM - 1; c++) {
        if (c < NC) issue(c, c);
        CP_COMMIT();
    }

    for (int c = 0; c < NC; c++) {
        CP_WAIT(S_GEMM - 2);
        __syncthreads();
        int cn = c + S_GEMM - 1;
        if (cn < NC) issue(cn, cn & (S_GEMM - 1));
        CP_COMMIT();

        uint32_t aOff = aAddr + (uint32_t)(c & (S_GEMM - 1)) * AS_STG;
        uint32_t bOff = bAddr + (uint32_t)(c & (S_GEMM - 1)) * WS_STG;
        #pragma unroll
        for (int s = 0; s < 4; s++) {
            uint32_t ko = s * 32;                    // 16 halves per k-slice
            uint32_t a0[4], a1[4], b0[4], b1[4];
            LDM4(a0, aOff + ko);
            LDM4(a1, aOff + ko + 16 * RS * 2);       // +16 m-rows
            LDM4(b0, bOff + ko);                     // n-tiles 0,1
            LDM4(b1, bOff + ko + 16 * RS * 2);       // n-tiles 2,3
            mma16(acc[0][0], a0, b0);     mma16(acc[0][1], a0, b0 + 2);
            mma16(acc[0][2], a0, b1);     mma16(acc[0][3], a0, b1 + 2);
            mma16(acc[1][0], a1, b0);     mma16(acc[1][1], a1, b0 + 2);
            mma16(acc[1][2], a1, b1);     mma16(acc[1][3], a1, b1 + 2);
        }
    }

    #pragma unroll
    for (int mt = 0; mt < 2; mt++) {
        int r0 = m0 + wm + mt * 16 + g;
        #pragma unroll
        for (int nt = 0; nt < 4; nt++) {
            int c0 = n0 + wn + nt * 8 + 2 * q;
            if (c0 < N) {
                float* d = acc[mt][nt];
                size_t o1 = (size_t)r0 * N + c0;
                size_t o2 = (size_t)(r0 + 8) * N + c0;
                if (ADD) {
                    C[o1] += d[0]; C[o1 + 1] += d[1];
                    C[o2] += d[2]; C[o2 + 1] += d[3];
                } else {
                    C[o1] = d[0]; C[o1 + 1] = d[1];
                    C[o2] = d[2]; C[o2 + 1] = d[3];
                }
            }
        }
    }
}

// ============ fused fp16 MLP GEMM: Gp = fp16(silu(A*W1^T) * (A*W3^T)) ============
#define S_MLP 3
#define SMEM_MLP (S_MLP*(AS_STG+2*WS_STG))   // 110592

__global__ void __launch_bounds__(256) k_mlp_tc(
        const __half* __restrict__ A,
        const __half* __restrict__ W1, const __half* __restrict__ W3,
        __half* __restrict__ Gp) {
    const int N = FFD, K = DD;
    extern __shared__ __align__(16) char smem[];
    uint32_t sA  = smem_u32(smem);
    uint32_t sW1 = sA + S_MLP * AS_STG;
    uint32_t sW3 = sW1 + S_MLP * WS_STG;

    int m0 = blockIdx.y * 128, n0 = blockIdx.x * 64;
    int tid = threadIdx.x;
    int lane = tid & 31, warp = tid >> 5;
    int wm = (warp & 3) * 32, wn = (warp >> 2) * 32;
    int g = lane >> 2, q = lane & 3;

    int arow = (lane & 7) + ((lane >> 3) & 1) * 8;
    int acolh = (lane >> 4) * 8;
    int brow = (lane & 7) + (lane >> 4) * 8;
    int bcolh = ((lane >> 3) & 1) * 8;
    uint32_t aAddr  = sA  + (uint32_t)((wm + arow) * RS + acolh) * 2;
    uint32_t b1Addr = sW1 + (uint32_t)((wn + brow) * RS + bcolh) * 2;
    uint32_t b3Addr = sW3 + (uint32_t)((wn + brow) * RS + bcolh) * 2;

    int crow = tid >> 3, c8 = tid & 7;
    uint32_t aDst = sA + (uint32_t)(crow * RS + c8 * 8) * 2;
    uint32_t wDst =      (uint32_t)(crow * RS + c8 * 8) * 2;

    int NC = (K + 63) >> 6;   // 5

    auto issue = [&](int c, int buf) {
        int kk = (c << 6) + c8 * 8;
        unsigned okk = (kk + 8 <= K) ? 16u : 0u;
        const __half* ap = A + (size_t)(m0 + crow) * K + (okk ? kk : 0);
        #pragma unroll
        for (int r = 0; r < 4; r++) {
            cp16(aDst + (uint32_t)buf * AS_STG + (uint32_t)r * 32 * RS * 2,
                 ap + (size_t)r * 32 * K, okk);
        }
        #pragma unroll
        for (int r = 0; r < 2; r++) {
            int row = n0 + crow + r * 32;
            unsigned sz = (okk && row < N) ? 16u : 0u;
            size_t off = sz ? ((size_t)row * K + kk) : 0;
            cp16(sW1 + wDst + (uint32_t)buf * WS_STG + (uint32_t)r * 32 * RS * 2, W1 + off, sz);
            cp16(sW3 + wDst + (uint32_t)buf * WS_STG + (uint32_t)r * 32 * RS * 2, W3 + off, sz);
        }
    };

    float acc1[2][4][4] = {};
    float acc3[2][4][4] = {};

    #pragma unroll
    for (int c = 0; c < S_MLP - 1; c++) {
        if (c < NC) issue(c, c);
        CP_COMMIT();
    }

    for (int c = 0; c < NC; c++) {
        CP_WAIT(S_MLP - 2);
        __syncthreads();
        int cn = c + S_MLP - 1;
        if (cn < NC) issue(cn, cn % S_MLP);
        CP_COMMIT();

        int buf = c % S_MLP;
        uint32_t aOff  = aAddr  + (uint32_t)buf * AS_STG;
        uint32_t b1Off = b1Addr + (uint32_t)buf * WS_STG;
        uint32_t b3Off = b3Addr + (uint32_t)buf * WS_STG;
        #pragma unroll
        for (int s = 0; s < 4; s++) {
            uint32_t ko = s * 32;
            uint32_t a0[4], a1[4], b0[4], b1[4], c0[4], c1[4];
            LDM4(a0, aOff + ko);
            LDM4(a1, aOff + ko + 16 * RS * 2);
            LDM4(b0, b1Off + ko);
            LDM4(b1, b1Off + ko + 16 * RS * 2);
            LDM4(c0, b3Off + ko);
            LDM4(c1, b3Off + ko + 16 * RS * 2);
            mma16(acc1[0][0], a0, b0);  mma16(acc1[0][1], a0, b0 + 2);
            mma16(acc1[0][2], a0, b1);  mma16(acc1[0][3], a0, b1 + 2);
            mma16(acc1[1][0], a1, b0);  mma16(acc1[1][1], a1, b0 + 2);
            mma16(acc1[1][2], a1, b1);  mma16(acc1[1][3], a1, b1 + 2);
            mma16(acc3[0][0], a0, c0);  mma16(acc3[0][1], a0, c0 + 2);
            mma16(acc3[0][2], a0, c1);  mma16(acc3[0][3], a0, c1 + 2);
            mma16(acc3[1][0], a1, c0);  mma16(acc3[1][1], a1, c0 + 2);
            mma16(acc3[1][2], a1, c1);  mma16(acc3[1][3], a1, c1 + 2);
        }
    }

    #pragma unroll
    for (int mt = 0; mt < 2; mt++) {
        int r0 = m0 + wm + mt * 16 + g;
        #pragma unroll
        for (int nt = 0; nt < 4; nt++) {
            int c0 = n0 + wn + nt * 8 + 2 * q;
            if (c0 < N) {
                float* dg = acc1[mt][nt];
                float* du = acc3[mt][nt];
                #pragma unroll
                for (int e = 0; e < 4; e++) {
                    float gg = dg[e], uu = du[e];
                    float sv = gg / (1.f + __expf(-gg));
                    int row = (e < 2) ? r0 : r0 + 8;
                    int col = c0 + (e & 1);
                    Gp[(size_t)row * N + col] = __float2half_rn(sv * uu);
                }
            }
        }
    }
}

// ---------------- embed ----------------
__global__ void k_embed(const int* __restrict__ idx, const float* __restrict__ emb,
                        float* __restrict__ x) {
    int i = blockIdx.x * 256 + threadIdx.x;
    if (i >= MM * DD) return;
    int m = i / DD;
    int d = i - m * DD;
    x[i] = emb[idx[m] * DD + d];
}

// ---------------- rope table ----------------
__global__ void k_rope(float* __restrict__ ct, float* __restrict__ st) {
    int i = blockIdx.x * 256 + threadIdx.x;
    if (i >= TT * 20) return;
    int t = i / 20, p = i % 20;
    float f = expf(-0.4605170186f * (float)p);   // 10000^{-p/20}
    float s, c;
    sincosf((float)t * f, &s, &c);
    ct[i] = c;
    st[i] = s;
}

// ---------------- rmsnorm: warp per row, 8 rows/block; fp16 output ----------------
__global__ void __launch_bounds__(256) k_rmsnorm(const float* __restrict__ x,
                                                 const float* __restrict__ w,
                                                 __half* __restrict__ out) {
    int m = blockIdx.x * 8 + (threadIdx.x >> 5);
    int lane = threadIdx.x & 31;
    const float* xr = x + (size_t)m * DD;
    float v[9];
    float ss = 0.f;
    #pragma unroll
    for (int j = 0; j < 9; j++) {
        int d = lane + 32 * j;
        v[j] = (d < DD) ? xr[d] : 0.f;
        ss += v[j] * v[j];
    }
    #pragma unroll
    for (int o = 16; o; o >>= 1) ss += __shfl_xor_sync(0xffffffffu, ss, o);
    float sc = rsqrtf(ss / (float)DD + 1e-6f);
    __half* orow = out + (size_t)m * DD;
    #pragma unroll
    for (int j = 0; j < 9; j++) {
        int d = lane + 32 * j;
        if (d < DD) orow[d] = __float2half_rn(v[j] * sc * w[d]);
    }
}

// ============ fused flash attention (rotary on load; fp16 output) ============
__global__ void __launch_bounds__(256) k_attn(const float* __restrict__ q,
                                              const float* __restrict__ k,
                                              const float* __restrict__ v,
                                              __half* __restrict__ o,
                                              const float* __restrict__ ct,
                                              const float* __restrict__ st) {
    int tt0 = blockIdx.x * 64;
    int bh = blockIdx.y;
    int b = bh / HH, h = bh - b * HH;
    const float* qb = q + (size_t)b * TT * DD + h * HDD;
    const float* kb = k + (size_t)b * TT * DD + h * HDD;
    const float* vb = v + (size_t)b * TT * DD + h * HDD;
    __half* ob      = o + ((size_t)b * TT + tt0) * DD + h * HDD;

    __shared__ float Qs[64][41];
    __shared__ float Ks[32][41];
    __shared__ float Vs[32][41];
    __shared__ float Ps[64][33];
    __shared__ float s_m[64], s_l[64], s_al[64];

    int tid = threadIdx.x;
    int lane = tid & 31, warp = tid >> 5;
    int tx = tid & 7, ty = tid >> 3;
    const float scale = 0.1581138830f;   // 40^-0.5

    for (int i = tid; i < 64 * HDD; i += 256) {
        int r = i / HDD, c = i - r * HDD;
        int t = tt0 + r;
        int p = (c < 20) ? c : c - 20;
        float cv = ct[t * 20 + p], sv = st[t * 20 + p];
        float a  = qb[(size_t)t * DD + c];
        float b2 = (c < 20) ? qb[(size_t)t * DD + c + 20] : qb[(size_t)t * DD + c - 20];
        float val = (c < 20) ? (a * cv - b2 * sv) : (a * cv + b2 * sv);
        Qs[r][c] = val * scale;
    }
    if (tid < 64) { s_m[tid] = -3.0e38f; s_l[tid] = 0.f; }
    __syncthreads();

    float accO[2][5] = {};
    int send = tt0 + 64;

    for (int s0 = 0; s0 < send; s0 += 32) {
        for (int i = tid; i < 32 * HDD; i += 256) {
            int r = i / HDD, c = i - r * HDD;
            int t = s0 + r;
            int p = (c < 20) ? c : c - 20;
            float cv = ct[t * 20 + p], sv = st[t * 20 + p];
            float a  = kb[(size_t)t * DD + c];
            float b2 = (c < 20) ? kb[(size_t)t * DD + c + 20] : kb[(size_t)t * DD + c - 20];
            Ks[r][c] = (c < 20) ? (a * cv - b2 * sv) : (a * cv + b2 * sv);
            Vs[r][c] = vb[(size_t)t * DD + c];
        }
        __syncthreads();

        // --- scores: warp handles 8 q-rows, lane = s within chunk ---
        float kreg[HDD];
        #pragma unroll
        for (int d = 0; d < HDD; d++) kreg[d] = Ks[lane][d];
        int sglob = s0 + lane;
        int r0 = warp * 8;
        #pragma unroll
        for (int ri = 0; ri < 8; ri++) {
            int rglob = tt0 + r0 + ri;
            float acc = 0.f;
            #pragma unroll
            for (int d = 0; d < HDD; d++) acc += Qs[r0 + ri][d] * kreg[d];
            float sv = (sglob <= rglob) ? acc : -1.0e30f;
            float mx = sv;
            #pragma unroll
            for (int off = 16; off; off >>= 1)
                mx = fmaxf(mx, __shfl_xor_sync(0xffffffffu, mx, off));
            float mold = s_m[r0 + ri];
            float mnew = fmaxf(mold, mx);
            float p = __expf(sv - mnew);
            float ps = p;
            #pragma unroll
            for (int off = 16; off; off >>= 1)
                ps += __shfl_xor_sync(0xffffffffu, ps, off);
            Ps[r0 + ri][lane] = p;
            if (lane == 0) {
                float al = __expf(mold - mnew);
                s_al[r0 + ri] = al;
                s_m[r0 + ri]  = mnew;
                s_l[r0 + ri]  = al * s_l[r0 + ri] + ps;
            }
        }
        __syncthreads();

        // --- O update: thread = (2 rows ty, 5 d-cols tx) ---
        float a0 = s_al[ty * 2], a1 = s_al[ty * 2 + 1];
        #pragma unroll
        for (int j = 0; j < 5; j++) { accO[0][j] *= a0; accO[1][j] *= a1; }
        #pragma unroll
        for (int kk = 0; kk < 32; kk++) {
            float p0 = Ps[ty * 2][kk];
            float p1 = Ps[ty * 2 + 1][kk];
            #pragma unroll
            for (int j = 0; j < 5; j++) {
                float vv = Vs[kk][tx * 5 + j];
                accO[0][j] += p0 * vv;
                accO[1][j] += p1 * vv;
            }
        }
        __syncthreads();
    }

    float inv0 = 1.f / s_l[ty * 2];
    float inv1 = 1.f / s_l[ty * 2 + 1];
    #pragma unroll
    for (int j = 0; j < 5; j++) {
        ob[(size_t)(ty * 2 + 0) * DD + tx * 5 + j] = __float2half_rn(accO[0][j] * inv0);
        ob[(size_t)(ty * 2 + 1) * DD + tx * 5 + j] = __float2half_rn(accO[1][j] * inv1);
    }
}

// ---------------- launcher ----------------
extern "C" void kernel_launch(void* const* d_in, const int* in_sizes, int n_in,
                              void* d_out, int out_size) {
    const int*   idx = (const int*)  d_in[0];
    const float* emb = (const float*)d_in[1];
    const float* wq  = (const float*)d_in[2];
    const float* wk  = (const float*)d_in[3];
    const float* wv  = (const float*)d_in[4];
    const float* wo  = (const float*)d_in[5];
    const float* w1  = (const float*)d_in[6];
    const float* w2  = (const float*)d_in[7];
    const float* w3  = (const float*)d_in[8];
    const float* n1  = (const float*)d_in[9];
    const float* n2  = (const float*)d_in[10];
    const float* nw  = (const float*)d_in[11];
    float* out = (float*)d_out;

    float *x, *q, *k, *v, *ct, *st;
    __half *h, *o, *gp, *wr;
    cudaGetSymbolAddress((void**)&x,  g_x);
    cudaGetSymbolAddress((void**)&h,  g_h);
    cudaGetSymbolAddress((void**)&q,  g_q);
    cudaGetSymbolAddress((void**)&k,  g_k);
    cudaGetSymbolAddress((void**)&v,  g_v);
    cudaGetSymbolAddress((void**)&o,  g_o);
    cudaGetSymbolAddress((void**)&gp, g_gp);
    cudaGetSymbolAddress((void**)&ct, g_ct);
    cudaGetSymbolAddress((void**)&st, g_st);
    cudaGetSymbolAddress((void**)&wr, g_wr);

    cudaFuncSetAttribute((const void*)k_gemm_tc<false>,
                         cudaFuncAttributeMaxDynamicSharedMemorySize, SMEM_GEMM);
    cudaFuncSetAttribute((const void*)k_gemm_tc<true>,
                         cudaFuncAttributeMaxDynamicSharedMemorySize, SMEM_GEMM);
    cudaFuncSetAttribute((const void*)k_mlp_tc,
                         cudaFuncAttributeMaxDynamicSharedMemorySize, SMEM_MLP);

    // pre-round all weights to fp16 once per launch
    const int NW_D = LL * DD * DD;    // 548800
    const int NW_F = LL * FFD * DD;   // 2195200
    k_round<<<(NW_D / 4 + 255) / 256, 256>>>(wq, wr + WR_Q, NW_D / 4);
    k_round<<<(NW_D / 4 + 255) / 256, 256>>>(wk, wr + WR_K, NW_D / 4);
    k_round<<<(NW_D / 4 + 255) / 256, 256>>>(wv, wr + WR_V, NW_D / 4);
    k_round<<<(NW_D / 4 + 255) / 256, 256>>>(wo, wr + WR_O, NW_D / 4);
    k_round<<<(NW_F / 4 + 255) / 256, 256>>>(w1, wr + WR_1, NW_F / 4);
    k_round<<<(NW_F / 4 + 255) / 256, 256>>>(w3, wr + WR_3, NW_F / 4);
    k_round<<<(NW_F / 4 + 255) / 256, 256>>>(w2, wr + WR_2, NW_F / 4);
    k_round<<<(VV * DD / 4 + 255) / 256, 256>>>(emb, wr + WR_E, VV * DD / 4);

    k_rope<<<(TT * 20 + 255) / 256, 256>>>(ct, st);
    k_embed<<<(MM * DD + 255) / 256, 256>>>(idx, emb, x);

    dim3 gQKV(5, MM / 128, 3);   // N = 280, 3 outputs
    dim3 gD  (5, MM / 128, 1);   // N = 280
    dim3 gF  (18, MM / 128);     // N = 1120 fused MLP
    dim3 gV  (4, MM / 128, 1);   // N = 256

    for (int l = 0; l < LL; l++) {
        size_t wOff = (size_t)l * DD * DD;
        size_t fOff = (size_t)l * FFD * DD;
        k_rmsnorm<<<MM / 8, 256>>>(x, n1 + l * DD, h);
        k_gemm_tc<false><<<gQKV, 256, SMEM_GEMM>>>(
            h, wr + WR_Q + wOff, wr + WR_K + wOff, wr + WR_V + wOff,
            q, k, v, DD, DD);
        k_attn<<<dim3(TT / 64, BB * HH), 256>>>(q, k, v, o, ct, st);
        k_gemm_tc<true><<<gD, 256, SMEM_GEMM>>>(
            o, wr + WR_O + wOff, 0, 0, x, 0, 0, DD, DD);
        k_rmsnorm<<<MM / 8, 256>>>(x, n2 + l * DD, h);
        k_mlp_tc<<<gF, 256, SMEM_MLP>>>(h, wr + WR_1 + fOff, wr + WR_3 + fOff, gp);
        k_gemm_tc<true><<<gD, 256, SMEM_GEMM>>>(
            gp, wr + WR_2 + fOff, 0, 0, x, 0, 0, DD, FFD);
    }

    k_rmsnorm<<<MM / 8, 256>>>(x, nw, h);
    k_gemm_tc<false><<<gV, 256, SMEM_GEMM>>>(
        h, wr + WR_E, 0, 0, out, 0, 0, VV, DD);
}